// round 1
// baseline (speedup 1.0000x reference)
#include <cuda_runtime.h>
#include <cuda_bf16.h>
#include <math.h>

// ---------------------------------------------------------------------------
// Problem constants (fixed by the dataset)
//   B=4, L=1024, d=1024, V=32000, NHEAD=16, hd=64, dff=2048, M = B*L = 4096
// ---------------------------------------------------------------------------
#define MROWS 4096
#define DMODEL 1024
#define VOCAB 32000
#define DFF 2048
#define NH 16
#define HD 64
#define LSEQ 1024

// Scratch in device globals (allocation-free rule)
__device__ float g_P[(long)MROWS * VOCAB];      // 524 MB: vocab probs / attn scores
__device__ float g_A[MROWS * DMODEL];
__device__ float g_tmp[MROWS * DMODEL];
__device__ float g_x1[MROWS * DMODEL];
__device__ float g_x2[MROWS * DMODEL];
__device__ float g_q[MROWS * DMODEL];
__device__ float g_k[MROWS * DMODEL];
__device__ float g_v[MROWS * DMODEL];
__device__ float g_y[MROWS * DMODEL];
__device__ float g_h[MROWS * DFF];

// ---------------------------------------------------------------------------
// General tiled SGEMM: C = epilogue( scale * A@B (+bias) (+addmat) )
//   A is [M,K] row-major. B is [K,N] (bT=0) or [N,K] (bT=1), row-major.
//   Batched via blockIdx.z with split offsets: off = (z/zInner)*sXo + (z%zInner)*sXi
//   Epilogue order: v = acc*scale; v += bias[n]; v += addmat[idx]; act(v);
//                   v = residual[idx] + alpha*v;  write (optionally head-permuted)
//   Requirements used here: M % 128 == 0, K % 16 == 0.  N guarded.
// ---------------------------------------------------------------------------
__global__ void __launch_bounds__(256) gemm_k(
    const float* __restrict__ A, const float* __restrict__ Bm, float* __restrict__ C,
    int M, int N, int K, int bT,
    long sAo, long sAi, long sBo, long sBi, long sCo, long sCi, int zInner, int ldc,
    const float* __restrict__ bias, const float* __restrict__ addmat,
    const float* __restrict__ residual, const float* __restrict__ alpha_ptr,
    float scale, int act, int permute)
{
    __shared__ float As[16][132];
    __shared__ float Bs[16][132];

    int z = blockIdx.z;
    int zo = z / zInner, zi = z % zInner;
    const float* Ab = A + zo * sAo + zi * sAi;
    const float* Bb = Bm + zo * sBo + zi * sBi;
    long cOff = zo * sCo + zi * sCi;

    int n0 = blockIdx.x * 128;
    int m0 = blockIdx.y * 128;
    int tid = threadIdx.x;
    int tx = tid & 15, ty = tid >> 4;

    float acc[8][8];
#pragma unroll
    for (int i = 0; i < 8; i++)
#pragma unroll
        for (int j = 0; j < 8; j++) acc[i][j] = 0.f;

    for (int k0 = 0; k0 < K; k0 += 16) {
        // ---- load A tile: 128x16, 512 float4 ----
#pragma unroll
        for (int it = 0; it < 2; it++) {
            int v = tid + it * 256;
            int row = v >> 2, kq = v & 3;
            float4 t = *(const float4*)&Ab[(long)(m0 + row) * K + k0 + kq * 4];
            As[kq * 4 + 0][row] = t.x;
            As[kq * 4 + 1][row] = t.y;
            As[kq * 4 + 2][row] = t.z;
            As[kq * 4 + 3][row] = t.w;
        }
        // ---- load B tile ----
        if (bT) {  // B is [N,K]
#pragma unroll
            for (int it = 0; it < 2; it++) {
                int v = tid + it * 256;
                int row = v >> 2, kq = v & 3;
                float4 t = make_float4(0.f, 0.f, 0.f, 0.f);
                if (n0 + row < N)
                    t = *(const float4*)&Bb[(long)(n0 + row) * K + k0 + kq * 4];
                Bs[kq * 4 + 0][row] = t.x;
                Bs[kq * 4 + 1][row] = t.y;
                Bs[kq * 4 + 2][row] = t.z;
                Bs[kq * 4 + 3][row] = t.w;
            }
        } else {  // B is [K,N]
#pragma unroll
            for (int it = 0; it < 2; it++) {
                int v = tid + it * 256;
                int kr = v >> 5, nq = v & 31;
                float4 t = make_float4(0.f, 0.f, 0.f, 0.f);
                int n = n0 + nq * 4;
                if (n < N)
                    t = *(const float4*)&Bb[(long)(k0 + kr) * N + n];
                *(float4*)&Bs[kr][nq * 4] = t;
            }
        }
        __syncthreads();

#pragma unroll
        for (int kk = 0; kk < 16; kk++) {
            float a[8], b[8];
            *(float4*)&a[0] = *(const float4*)&As[kk][ty * 8];
            *(float4*)&a[4] = *(const float4*)&As[kk][ty * 8 + 4];
            *(float4*)&b[0] = *(const float4*)&Bs[kk][tx * 8];
            *(float4*)&b[4] = *(const float4*)&Bs[kk][tx * 8 + 4];
#pragma unroll
            for (int i = 0; i < 8; i++)
#pragma unroll
                for (int j = 0; j < 8; j++) acc[i][j] += a[i] * b[j];
        }
        __syncthreads();
    }

    float alpha = alpha_ptr ? *alpha_ptr : 1.0f;

#pragma unroll
    for (int i = 0; i < 8; i++) {
        int m = m0 + ty * 8 + i;
#pragma unroll
        for (int j = 0; j < 8; j++) {
            int n = n0 + tx * 8 + j;
            if (n >= N) continue;
            float v = acc[i][j] * scale;
            if (bias) v += bias[n];
            long idx = cOff + (long)m * ldc + n;
            if (addmat) v += addmat[idx];
            if (act == 1) v = fmaxf(v, 0.f);
            else if (act == 2) v = v > 0.f ? v : 0.01f * v;
            if (residual) v = residual[idx] + alpha * v;
            if (permute) {
                // [M,d] -> [B, H, L, hd]
                int bb = m >> 10, l = m & 1023, h = n >> 6, dd = n & 63;
                C[(((long)(bb * NH + h)) * LSEQ + l) * HD + dd] = v;
            } else {
                C[idx] = v;
            }
        }
    }
}

// ---------------------------------------------------------------------------
// Row softmax, in place. One CTA per row, online max/sum then normalize pass.
// ---------------------------------------------------------------------------
__global__ void __launch_bounds__(256) softmax_k(float* __restrict__ data, int ncols)
{
    long row = blockIdx.x;
    float* p = data + row * (long)ncols;
    int tid = threadIdx.x;

    float m = -1e30f, s = 0.f;
    for (int i = tid; i < ncols; i += 256) {
        float v = p[i];
        if (v > m) { s *= __expf(m - v); m = v; }
        s += __expf(v - m);
    }
    __shared__ float sm[256], ss[256];
    sm[tid] = m; ss[tid] = s;
    __syncthreads();
    for (int o = 128; o > 0; o >>= 1) {
        if (tid < o) {
            float m2 = sm[tid + o], s2 = ss[tid + o];
            float mm = fmaxf(sm[tid], m2);
            ss[tid] = ss[tid] * __expf(sm[tid] - mm) + s2 * __expf(m2 - mm);
            sm[tid] = mm;
        }
        __syncthreads();
    }
    float gm = sm[0];
    float inv = 1.0f / ss[0];
    for (int i = tid; i < ncols; i += 256)
        p[i] = __expf(p[i] - gm) * inv;
}

// ---------------------------------------------------------------------------
// Host-side launch helpers
// ---------------------------------------------------------------------------
static void gemm(const float* A, const float* B, float* C,
                 int M, int N, int K, bool bT,
                 int batch = 1,
                 long sAo = 0, long sAi = 0, long sBo = 0, long sBi = 0,
                 long sCo = 0, long sCi = 0, int zInner = 1,
                 int ldc = 0,
                 const float* bias = nullptr, const float* addmat = nullptr,
                 const float* residual = nullptr, const float* alpha = nullptr,
                 float scale = 1.0f, int act = 0, int permute = 0)
{
    if (ldc == 0) ldc = N;
    dim3 grid((N + 127) / 128, (M + 127) / 128, batch);
    gemm_k<<<grid, 256>>>(A, B, C, M, N, K, bT ? 1 : 0,
                          sAo, sAi, sBo, sBi, sCo, sCi, zInner, ldc,
                          bias, addmat, residual, alpha, scale, act, permute);
}

extern "C" void kernel_launch(void* const* d_in, const int* in_sizes, int n_in,
                              void* d_out, int out_size)
{
    const float* tgt   = (const float*)d_in[0];
    const float* src   = (const float*)d_in[1];
    const float* emb   = (const float*)d_in[2];
    const float* va_w  = (const float*)d_in[3];
    const float* va_b  = (const float*)d_in[4];
    const float* a_va  = (const float*)d_in[5];
    const float* sa_wq = (const float*)d_in[6];
    const float* sa_bq = (const float*)d_in[7];
    const float* sa_wk = (const float*)d_in[8];
    const float* sa_bk = (const float*)d_in[9];
    const float* sa_wv = (const float*)d_in[10];
    const float* sa_bv = (const float*)d_in[11];
    const float* sa_wo = (const float*)d_in[12];
    const float* sa_bo = (const float*)d_in[13];
    const float* a_sa  = (const float*)d_in[14];
    const float* ca_wq = (const float*)d_in[15];
    const float* ca_bq = (const float*)d_in[16];
    const float* ca_wk = (const float*)d_in[17];
    const float* ca_bk = (const float*)d_in[18];
    const float* ca_wv = (const float*)d_in[19];
    const float* ca_bv = (const float*)d_in[20];
    const float* ca_wo = (const float*)d_in[21];
    const float* ca_bo = (const float*)d_in[22];
    const float* a_ca  = (const float*)d_in[23];
    const float* ff_w1 = (const float*)d_in[24];
    const float* ff_b1 = (const float*)d_in[25];
    const float* ff_w2 = (const float*)d_in[26];
    const float* ff_b2 = (const float*)d_in[27];
    const float* a_ff  = (const float*)d_in[28];
    float* out = (float*)d_out;

    void* p;
    cudaGetSymbolAddress(&p, g_P);   float* P   = (float*)p;
    cudaGetSymbolAddress(&p, g_A);   float* Av  = (float*)p;
    cudaGetSymbolAddress(&p, g_tmp); float* tmp = (float*)p;
    cudaGetSymbolAddress(&p, g_x1);  float* x1  = (float*)p;
    cudaGetSymbolAddress(&p, g_x2);  float* x2  = (float*)p;
    cudaGetSymbolAddress(&p, g_q);   float* q   = (float*)p;
    cudaGetSymbolAddress(&p, g_k);   float* k   = (float*)p;
    cudaGetSymbolAddress(&p, g_v);   float* v   = (float*)p;
    cudaGetSymbolAddress(&p, g_y);   float* y   = (float*)p;
    cudaGetSymbolAddress(&p, g_h);   float* h   = (float*)p;

    const float inv_sqrt_d = 1.0f / 32.0f;  // 1/sqrt(1024)  (FULL dim, per ref)
    const long sQ = (long)LSEQ * HD;        // per-(b,h) q/k/v stride = 65536
    const long sS = (long)LSEQ * LSEQ;      // per-(b,h) score stride = 1048576

    // ===== Vocabulary attention =====
    // logits = tgt @ emb^T  -> P [4096, 32000]
    gemm(tgt, emb, P, MROWS, VOCAB, DMODEL, /*bT=*/true);
    softmax_k<<<MROWS, 256>>>(P, VOCAB);
    // A = P @ emb  [4096, 1024]
    gemm(P, emb, Av, MROWS, DMODEL, VOCAB, false);
    // tmp = A @ va_w[1024:2048]
    gemm(Av, va_w + (long)DMODEL * DMODEL, tmp, MROWS, DMODEL, DMODEL, false);
    // x1 = tgt + alpha_va * (tgt @ va_w[0:1024] + tmp + va_b)
    gemm(tgt, va_w, x1, MROWS, DMODEL, DMODEL, false, 1, 0,0,0,0,0,0,1, DMODEL,
         va_b, tmp, tgt, a_va);

    // ===== Self attention =====
    gemm(x1, sa_wq, q, MROWS, DMODEL, DMODEL, false, 1, 0,0,0,0,0,0,1, DMODEL,
         sa_bq, nullptr, nullptr, nullptr, 1.f, /*relu*/1, /*permute*/1);
    gemm(x1, sa_wk, k, MROWS, DMODEL, DMODEL, false, 1, 0,0,0,0,0,0,1, DMODEL,
         sa_bk, nullptr, nullptr, nullptr, 1.f, 1, 1);
    gemm(x1, sa_wv, v, MROWS, DMODEL, DMODEL, false, 1, 0,0,0,0,0,0,1, DMODEL,
         sa_bv, nullptr, nullptr, nullptr, 1.f, 1, 1);
    // scores[z] = q_z @ k_z^T / 32   (64 batches)
    gemm(q, k, P, LSEQ, LSEQ, HD, true, NH * 4,
         sQ, 0, sQ, 0, sS, 0, 1, LSEQ,
         nullptr, nullptr, nullptr, nullptr, inv_sqrt_d);
    softmax_k<<<NH * 4 * LSEQ, 256>>>(P, LSEQ);
    // y_z = P_z @ v_z  -> un-permuted [4096, 1024]
    gemm(P, v, y, LSEQ, HD, LSEQ, false, NH * 4,
         sS * NH, sS, sQ * NH, sQ,
         (long)LSEQ * DMODEL, HD, NH, DMODEL);
    // x2 = x1 + alpha_sa * relu(y @ wo + bo)
    gemm(y, sa_wo, x2, MROWS, DMODEL, DMODEL, false, 1, 0,0,0,0,0,0,1, DMODEL,
         sa_bo, nullptr, x1, a_sa, 1.f, 1, 0);

    // ===== Cross attention (q from x2, k/v from src) =====
    gemm(x2, ca_wq, q, MROWS, DMODEL, DMODEL, false, 1, 0,0,0,0,0,0,1, DMODEL,
         ca_bq, nullptr, nullptr, nullptr, 1.f, 1, 1);
    gemm(src, ca_wk, k, MROWS, DMODEL, DMODEL, false, 1, 0,0,0,0,0,0,1, DMODEL,
         ca_bk, nullptr, nullptr, nullptr, 1.f, 1, 1);
    gemm(src, ca_wv, v, MROWS, DMODEL, DMODEL, false, 1, 0,0,0,0,0,0,1, DMODEL,
         ca_bv, nullptr, nullptr, nullptr, 1.f, 1, 1);
    gemm(q, k, P, LSEQ, LSEQ, HD, true, NH * 4,
         sQ, 0, sQ, 0, sS, 0, 1, LSEQ,
         nullptr, nullptr, nullptr, nullptr, inv_sqrt_d);
    softmax_k<<<NH * 4 * LSEQ, 256>>>(P, LSEQ);
    gemm(P, v, y, LSEQ, HD, LSEQ, false, NH * 4,
         sS * NH, sS, sQ * NH, sQ,
         (long)LSEQ * DMODEL, HD, NH, DMODEL);
    // x3 (reuse x1) = x2 + alpha_ca * relu(y @ wo + bo)
    gemm(y, ca_wo, x1, MROWS, DMODEL, DMODEL, false, 1, 0,0,0,0,0,0,1, DMODEL,
         ca_bo, nullptr, x2, a_ca, 1.f, 1, 0);

    // ===== Feed forward =====
    gemm(x1, ff_w1, h, MROWS, DFF, DMODEL, false, 1, 0,0,0,0,0,0,1, DFF,
         ff_b1, nullptr, nullptr, nullptr, 1.f, /*leaky*/2, 0);
    gemm(h, ff_w2, out, MROWS, DMODEL, DFF, false, 1, 0,0,0,0,0,0,1, DMODEL,
         ff_b2, nullptr, x1, a_ff, 1.f, 0, 0);
}